// round 7
// baseline (speedup 1.0000x reference)
#include <cuda_runtime.h>

// out = noised + 0.1f * noise over 50,331,648 fp32 (12,582,912 float4).
// HBM-floor stream. Persistent grid-stride form: exact-fill grid
// (SMs x 8 CTAs x 256 thr) -> single wave, no wave transitions, steady
// per-warp load stream. Low-register body with streaming cache hints.

__global__ void __launch_bounds__(256, 8) gnoise_kernel(
    const float4* __restrict__ noised,
    const float4* __restrict__ noise,
    float4* __restrict__ out,
    int n4,   // n / 4
    int n)    // total elements
{
    int stride = gridDim.x * blockDim.x;
    int i = blockIdx.x * blockDim.x + threadIdx.x;

    for (; i < n4; i += stride) {
        float4 a = __ldcs(noised + i);
        float4 b = __ldcs(noise + i);
        float4 r;
        r.x = fmaf(0.1f, b.x, a.x);
        r.y = fmaf(0.1f, b.y, a.y);
        r.z = fmaf(0.1f, b.z, a.z);
        r.w = fmaf(0.1f, b.w, a.w);
        __stcs(out + i, r);
    }

    // Scalar tail: elements [4*n4, n). Empty when n % 4 == 0.
    if (blockIdx.x == 0 && threadIdx.x == 0) {
        const float* ns = (const float*)noised;
        const float* nz = (const float*)noise;
        float* o = (float*)out;
        for (int j = 4 * n4; j < n; j++)
            o[j] = fmaf(0.1f, nz[j], ns[j]);
    }
}

extern "C" void kernel_launch(void* const* d_in, const int* in_sizes, int n_in,
                              void* d_out, int out_size)
{
    const float* noised = (const float*)d_in[0];
    const float* noise  = (const float*)d_in[1];
    float* out = (float*)d_out;
    int n = in_sizes[0];

    int n4 = n / 4;

    int sm_count = 148;
    cudaDeviceGetAttribute(&sm_count, cudaDevAttrMultiProcessorCount, 0);

    const int threads = 256;
    int blocks = sm_count * 8;  // exact-fill: 8 CTAs of 256 thr per SM
    int max_blocks = (n4 + threads - 1) / threads;
    if (blocks > max_blocks) blocks = max_blocks;
    if (blocks < 1) blocks = 1;

    gnoise_kernel<<<blocks, threads>>>(
        (const float4*)noised, (const float4*)noise, (float4*)out, n4, n);
}

// round 11
// speedup vs baseline: 1.0678x; 1.0678x over previous
#include <cuda_runtime.h>

// out = noised + 0.1f * noise over 50,331,648 fp32.
// HBM-floor stream. 256-bit (v8.f32) loads/stores: same bytes, half the
// L1tex wavefronts/instructions of the float4 version. One 8-float chunk
// per thread, one-shot grid (no loop) to maximize independent in-flight
// loads across blocks.

__global__ void __launch_bounds__(256) gnoise_kernel(
    const float* __restrict__ noised,
    const float* __restrict__ noise,
    float* __restrict__ out,
    int n8,   // n / 8
    int n)    // total elements
{
    int i = blockIdx.x * blockDim.x + threadIdx.x;
    if (i < n8) {
        const float* pa = noised + (size_t)i * 8;
        const float* pb = noise  + (size_t)i * 8;
        float* po = out + (size_t)i * 8;

        float a0, a1, a2, a3, a4, a5, a6, a7;
        float b0, b1, b2, b3, b4, b5, b6, b7;

        asm volatile("ld.global.nc.v8.f32 {%0,%1,%2,%3,%4,%5,%6,%7}, [%8];"
                     : "=f"(a0), "=f"(a1), "=f"(a2), "=f"(a3),
                       "=f"(a4), "=f"(a5), "=f"(a6), "=f"(a7)
                     : "l"(pa));
        asm volatile("ld.global.nc.v8.f32 {%0,%1,%2,%3,%4,%5,%6,%7}, [%8];"
                     : "=f"(b0), "=f"(b1), "=f"(b2), "=f"(b3),
                       "=f"(b4), "=f"(b5), "=f"(b6), "=f"(b7)
                     : "l"(pb));

        float r0 = fmaf(0.1f, b0, a0);
        float r1 = fmaf(0.1f, b1, a1);
        float r2 = fmaf(0.1f, b2, a2);
        float r3 = fmaf(0.1f, b3, a3);
        float r4 = fmaf(0.1f, b4, a4);
        float r5 = fmaf(0.1f, b5, a5);
        float r6 = fmaf(0.1f, b6, a6);
        float r7 = fmaf(0.1f, b7, a7);

        asm volatile("st.global.cs.v8.f32 [%0], {%1,%2,%3,%4,%5,%6,%7,%8};"
                     :: "l"(po),
                        "f"(r0), "f"(r1), "f"(r2), "f"(r3),
                        "f"(r4), "f"(r5), "f"(r6), "f"(r7)
                     : "memory");
    } else if (i == n8) {
        // Scalar tail: elements [8*n8, n). Empty when n % 8 == 0.
        for (int j = 8 * n8; j < n; j++)
            out[j] = fmaf(0.1f, noise[j], noised[j]);
    }
}

extern "C" void kernel_launch(void* const* d_in, const int* in_sizes, int n_in,
                              void* d_out, int out_size)
{
    const float* noised = (const float*)d_in[0];
    const float* noise  = (const float*)d_in[1];
    float* out = (float*)d_out;
    int n = in_sizes[0];

    int n8 = n / 8;
    int work = n8 + ((n & 7) ? 1 : 0);
    if (work == 0) return;
    const int threads = 256;
    int blocks = (work + threads - 1) / threads;
    gnoise_kernel<<<blocks, threads>>>(noised, noise, out, n8, n);
}